// round 7
// baseline (speedup 1.0000x reference)
#include <cuda_runtime.h>
#include <cstdint>

#define TT 2048
#define BB 128
#define HH 200
#define HP 208        // padded neuron count (13 warps * 32 / 2)
#define KH 100        // k-half span

typedef unsigned long long ull;

__device__ __forceinline__ void fma2(ull& acc, ull a, ull b) {
    asm("fma.rn.f32x2 %0, %1, %2, %0;" : "+l"(acc) : "l"(a), "l"(b));
}
__device__ __forceinline__ void unpack2(ull v, float& lo, float& hi) {
    asm("mov.b64 {%0,%1}, %2;" : "=f"(lo), "=f"(hi) : "l"(v));
}
__device__ __forceinline__ float tanh_hw(float x) {
    float r; asm("tanh.approx.f32 %0, %1;" : "=f"(r) : "f"(x));
    return r;
}

// 448 threads = 14 warps, one CTA per batch row.
//  tid < 416: compute. j = tid>>1 (0..207, j>=200 are zero pads), kh = tid&1.
//    Thread holds W_hh[j, 100kh : 100kh+100) in 50 u64 regs; computes half of
//    neuron j's dot; halves combined with one shfl_xor(1) (lanes 2m / 2m+1).
//  warp 13 (tid >= 416): output head for step t-1, overlapped.
// Double-buffered h => ONE __syncthreads per step.
__global__ void __launch_bounds__(448, 1) rnn_kernel(
    const float* __restrict__ x,     // [T, B, 2]
    const float* __restrict__ Wih,   // [H, 2]
    const float* __restrict__ Whh,   // [H, H]
    const float* __restrict__ bih,   // [H]
    const float* __restrict__ bhh,   // [H]
    const float* __restrict__ Wout,  // [1, H]
    const float* __restrict__ bOut,  // [1]
    float* __restrict__ out)         // [T, B, 1]
{
    __shared__ __align__(16) float2 xsm[TT];        // 16 KB input sequence
    __shared__ __align__(16) float  hsm[2][HP];     // double-buffered hidden state
    __shared__ __align__(16) float  houtsm[2][HP];  // h_j * Wout_j, parity buffers

    const int tid  = threadIdx.x;
    const int b    = blockIdx.x;
    const int lane = tid & 31;
    const int j    = tid >> 1;
    const int kh   = tid & 1;
    const bool compute = (tid < 416);
    const bool valid   = compute && (j < HH);
    const bool even    = (kh == 0);

    // Preload this batch's input sequence
    for (int i = tid; i < TT; i += 448)
        xsm[i] = *(const float2*)(x + ((size_t)i * BB + b) * 2);

    // W_hh[j, kh*100 : kh*100+100) as 50 packed fp32 pairs (8B-aligned)
    ull wr[50];
    {
        const ull* wrow = (const ull*)(Whh + (size_t)j * HH + kh * KH);
#pragma unroll
        for (int i = 0; i < 50; i++) wr[i] = valid ? wrow[i] : 0ull;
    }

    float wih0 = 0.f, wih1 = 0.f, bias = 0.f, wout = 0.f;
    if (valid) {
        wih0 = Wih[2 * j];
        wih1 = Wih[2 * j + 1];
        bias = bih[j] + bhh[j];
        wout = Wout[j];
    }
    const float bo = bOut[0];

    // h_0 = 0 (zero both buffers; pads included)
    for (int i = tid; i < 2 * HP; i += 448) ((float*)hsm)[i] = 0.0f;
    __syncthreads();

#pragma unroll 1
    for (int t = 0; t < TT; t++) {
        const int rp = t & 1;          // read h from hsm[rp], write to hsm[rp^1]
        if (compute) {
            // 25 LDS.128 over this k-half; even/odd lanes hit disjoint banks
            const ulonglong2* hp = (const ulonglong2*)(&hsm[rp][kh * KH]);
            ull a0 = 0ull, a1 = 0ull;
#pragma unroll
            for (int i = 0; i < 25; i++) {
                ulonglong2 hv = hp[i];
                fma2(a0, hv.x, wr[2 * i]);
                fma2(a1, hv.y, wr[2 * i + 1]);
            }
            float s0, s1, s2, s3;
            unpack2(a0, s0, s1);
            unpack2(a1, s2, s3);
            float s = (s0 + s1) + (s2 + s3);
            s += __shfl_xor_sync(0xFFFFFFFFu, s, 1);   // combine k-halves
            float2 xv = xsm[t];
            float pre = fmaf(xv.x, wih0, fmaf(xv.y, wih1, s + bias));
            float h = tanh_hw(pre);
            if (even) {                                 // one writer per neuron
                hsm[rp ^ 1][j] = h;
                houtsm[t & 1][j] = h * wout;
            }
        } else if (t > 0) {
            // warp 13: out[t-1,b] = sum_j houtsm[(t-1)&1][j] + bout
            const float* hv = houtsm[(t - 1) & 1];
            float acc = 0.0f;
#pragma unroll
            for (int i = 0; i < 7; i++) {
                int idx = lane + 32 * i;
                if (idx < HH) acc += hv[idx];
            }
#pragma unroll
            for (int off = 16; off; off >>= 1)
                acc += __shfl_xor_sync(0xFFFFFFFFu, acc, off);
            if (lane == 0) out[(size_t)(t - 1) * BB + b] = acc + bo;
        }
        __syncthreads();
    }

    // Final step's output (t = TT-1)
    if (!compute) {
        const float* hv = houtsm[(TT - 1) & 1];
        float acc = 0.0f;
#pragma unroll
        for (int i = 0; i < 7; i++) {
            int idx = lane + 32 * i;
            if (idx < HH) acc += hv[idx];
        }
#pragma unroll
        for (int off = 16; off; off >>= 1)
            acc += __shfl_xor_sync(0xFFFFFFFFu, acc, off);
        if (lane == 0) out[(size_t)(TT - 1) * BB + b] = acc + bo;
    }
}

extern "C" void kernel_launch(void* const* d_in, const int* in_sizes, int n_in,
                              void* d_out, int out_size) {
    const float* input_seq = (const float*)d_in[0];  // [T,B,2]
    const float* W_ih      = (const float*)d_in[1];  // [H,2]
    const float* W_hh      = (const float*)d_in[2];  // [H,H]
    const float* b_ih      = (const float*)d_in[3];  // [H]
    const float* b_hh      = (const float*)d_in[4];  // [H]
    const float* W_out     = (const float*)d_in[5];  // [1,H]
    const float* b_out     = (const float*)d_in[6];  // [1]
    float* out = (float*)d_out;                      // [T,B,1]

    rnn_kernel<<<BB, 448>>>(input_seq, W_ih, W_hh, b_ih, b_hh, W_out, b_out, out);
}